// round 3
// baseline (speedup 1.0000x reference)
#include <cuda_runtime.h>

// ---------------------------------------------------------------------------
// DPSOM fused kernel, round 3.
// Changes vs R2 (which failed by 1-2 argmin tie-flips, rel_err 1.109e-3):
//  * SOM distances now use the REFERENCE's expansion form in fp32:
//        d = (zz - 2*dot(z,p)) + pp
//    with dot accumulated sequentially (cuBLAS k-order) and pp reduced in
//    warp-shuffle-tree order (XLA row-reduce order) -> rounding noise
//    correlated with the reference, eliminating tie flips.
//  * GEMM2 / decoder-table accumulate from 0 and add bias in the epilogue
//    (cuBLAS semantics) instead of initializing the accumulator with bias.
//  * decoder table uses accurate expf.
// ---------------------------------------------------------------------------

#define BATCH   65536
#define K1      784
#define HID     256
#define LAT     32
#define NPROTO  25
#define BM      32
#define NTHR    256

#define XS_FLOATS   (K1 * 16 * 2)                 // 25088 floats
#define OFF_PROTO   (XS_FLOATS)                   // 25088
#define OFF_ZS      (OFF_PROTO + NPROTO * LAT)    // 25888
#define OFF_DS      (OFF_ZS + BM * LAT)           // 26912
#define OFF_PN      (OFF_DS + BM * NPROTO)        // 27712
#define OFF_ZZ      (OFF_PN + 32)                 // 27744 (pad pn to 32)
#define OFF_WIN     (OFF_ZZ + BM)                 // 27776
#define SMEM_FLOATS (OFF_WIN + BM)                // 27808
#define SMEM_BYTES  (SMEM_FLOATS * 4)             // 111232

__device__ float4 g_recon_table4[NPROTO * (K1 / 4)];

__global__ void decoder_table_kernel(const float* __restrict__ Wd1,
                                     const float* __restrict__ bd1,
                                     const float* __restrict__ Wd2,
                                     const float* __restrict__ bd2,
                                     const float* __restrict__ proto) {
    __shared__ float p[LAT];
    __shared__ float hd[HID];
    const int pid = blockIdx.x;
    const int t = threadIdx.x;
    if (t < LAT) p[t] = proto[pid * LAT + t];
    __syncthreads();
    if (t < HID) {
        float acc = 0.0f;
#pragma unroll
        for (int l = 0; l < LAT; l++) acc = fmaf(p[l], Wd1[l * HID + t], acc);
        hd[t] = fmaxf(acc + bd1[t], 0.0f);  // bias in epilogue, then ReLU
    }
    __syncthreads();
    float* gt = (float*)g_recon_table4;
    for (int o = t; o < K1; o += NTHR) {
        float acc = 0.0f;
#pragma unroll 8
        for (int n = 0; n < HID; n++) acc = fmaf(hd[n], Wd2[n * K1 + o], acc);
        float v = acc + bd2[o];
        gt[pid * K1 + o] = 1.0f / (1.0f + expf(-v));
    }
}

__global__ void __launch_bounds__(NTHR)
dpsom_main_kernel(const float* __restrict__ x,
                  const float* __restrict__ We1,
                  const float* __restrict__ be1,
                  const float* __restrict__ We2,
                  const float* __restrict__ be2,
                  const float* __restrict__ proto,
                  float* __restrict__ out) {
    extern __shared__ float smemf[];
    float* proto_s = smemf + OFF_PROTO;
    float* zs      = smemf + OFF_ZS;
    float* ds      = smemf + OFF_DS;
    float* pn      = smemf + OFF_PN;
    float* zzs     = smemf + OFF_ZZ;
    int*   win     = (int*)(smemf + OFF_WIN);

    const int t    = threadIdx.x;
    const int row0 = blockIdx.x * BM;

    // -------- stage x tile (layout: float offset k*32 + r) + prototypes -----
    {
        const float4* xrow4 = (const float4*)(x + (size_t)row0 * K1);
        for (int idx = t; idx < BM * (K1 / 4); idx += NTHR) {
            int r = idx / (K1 / 4);
            int q = idx - r * (K1 / 4);
            float4 v = xrow4[r * (K1 / 4) + q];
            float* dst = smemf + r;
            int k = q * 4;
            dst[(k + 0) * 32] = v.x;
            dst[(k + 1) * 32] = v.y;
            dst[(k + 2) * 32] = v.z;
            dst[(k + 3) * 32] = v.w;
        }
        for (int idx = t; idx < NPROTO * LAT; idx += NTHR) proto_s[idx] = proto[idx];
    }
    __syncthreads();

    // -------- GEMM1: one hidden column per thread, 32 rows in 16 f32x2 accs --
    unsigned long long acc[16];
#pragma unroll
    for (int q = 0; q < 16; q++) acc[q] = 0ull;
    {
        const float* w1p = We1 + t;  // column t of We1 [K1 x HID]
        const ulonglong2* xsv = (const ulonglong2*)smemf;
#pragma unroll 1
        for (int k = 0; k < K1; k += 4) {
            float w[4];
#pragma unroll
            for (int j = 0; j < 4; j++) w[j] = w1p[(k + j) * HID];
#pragma unroll
            for (int j = 0; j < 4; j++) {
                unsigned long long wp;
                asm("mov.b64 %0, {%1, %1};" : "=l"(wp) : "f"(w[j]));
                const ulonglong2* xk = xsv + (k + j) * 8;
#pragma unroll
                for (int q = 0; q < 8; q++) {
                    ulonglong2 v = xk[q];
                    asm("fma.rn.f32x2 %0, %1, %2, %0;" : "+l"(acc[2 * q])     : "l"(v.x), "l"(wp));
                    asm("fma.rn.f32x2 %0, %1, %2, %0;" : "+l"(acc[2 * q + 1]) : "l"(v.y), "l"(wp));
                }
            }
        }
    }

    // -------- bias + ReLU -> h in SMEM (aliases xs region); load We2 --------
    const float b1v = be1[t];
    __syncthreads();  // all xs reads done before aliasing
    float* hs   = smemf;                // [BM][HID]
    float* we2s = smemf + BM * HID;     // [HID][LAT]
#pragma unroll
    for (int q = 0; q < 16; q++) {
        float lo, hi;
        asm("mov.b64 {%0, %1}, %2;" : "=f"(lo), "=f"(hi) : "l"(acc[q]));
        hs[(2 * q) * HID + t]     = fmaxf(lo + b1v, 0.0f);
        hs[(2 * q + 1) * HID + t] = fmaxf(hi + b1v, 0.0f);
    }
    for (int idx = t; idx < HID * LAT; idx += NTHR) we2s[idx] = We2[idx];
    __syncthreads();

    // -------- GEMM2: thread -> (row r, 4 latent cols); bias in epilogue -----
    {
        const int r  = t >> 3;
        const int mb = (t & 7) << 2;
        float4 a = make_float4(0.0f, 0.0f, 0.0f, 0.0f);
        const float* hrow = hs + r * HID;
        const float4* w2v = (const float4*)we2s;
#pragma unroll 4
        for (int n = 0; n < HID; n++) {
            float hv  = hrow[n];
            float4 wv = w2v[n * (LAT / 4) + (mb >> 2)];
            a.x = fmaf(hv, wv.x, a.x);
            a.y = fmaf(hv, wv.y, a.y);
            a.z = fmaf(hv, wv.z, a.z);
            a.w = fmaf(hv, wv.w, a.w);
        }
        a.x += be2[mb]; a.y += be2[mb + 1]; a.z += be2[mb + 2]; a.w += be2[mb + 3];
        *(float4*)(zs + r * LAT + mb) = a;
        float* out_z = out + (size_t)BATCH * K1;
        *(float4*)(out_z + (size_t)(row0 + r) * LAT + mb) = a;
    }
    __syncthreads();

    // -------- pp_j in warp-shuffle-tree order (XLA row-reduce order) --------
    if (t < NPROTO) {
        const float* pj = proto_s + t * LAT;
        float a[32];
#pragma unroll
        for (int l = 0; l < 32; l++) a[l] = pj[l] * pj[l];
#pragma unroll
        for (int off = 16; off >= 1; off >>= 1)
#pragma unroll
            for (int i = 0; i < 16; i++)
                if (i < off) a[i] += a[i + off];
        pn[t] = a[0];
    }
    // zz per row: order is argmin-irrelevant (constant per-row offset)
    if (t >= 32 && t < 64) {
        int rr = t - 32;
        const float* zr = zs + rr * LAT;
        float s = 0.0f;
#pragma unroll
        for (int l = 0; l < LAT; l++) s = fmaf(zr[l], zr[l], s);
        zzs[rr] = s;
    }
    __syncthreads();

    // -------- distances in REFERENCE form: d = (zz - 2*dot) + pp ------------
    for (int idx = t; idx < BM * NPROTO; idx += NTHR) {
        int rr = idx / NPROTO;
        int j  = idx - rr * NPROTO;
        const float* zr = zs + rr * LAT;
        const float* pj = proto_s + j * LAT;
        float dot = 0.0f;
#pragma unroll
        for (int l = 0; l < LAT; l++) dot = fmaf(zr[l], pj[l], dot);
        ds[idx] = (zzs[rr] - 2.0f * dot) + pn[j];
    }
    __syncthreads();

    // -------- argmin per row (strict < => first-min, matches jnp.argmin) ----
    if (t < BM) {
        const float* dr = ds + t * NPROTO;
        float best = dr[0];
        int bi = 0;
#pragma unroll
        for (int j = 1; j < NPROTO; j++) {
            float v = dr[j];
            if (v < best) { best = v; bi = j; }
        }
        win[t] = bi;
    }
    __syncthreads();

    // -------- write som_z and x_recon (gather from decoder table) --------
    {
        float* out_som = out + (size_t)BATCH * (K1 + LAT);
        for (int idx = t; idx < BM * LAT; idx += NTHR) {
            int rr = idx >> 5, l = idx & (LAT - 1);
            out_som[(size_t)(row0 + rr) * LAT + l] = proto_s[win[rr] * LAT + l];
        }
        const float4* tab = (const float4*)g_recon_table4;
        float4* outr = (float4*)out;
        for (int idx = t; idx < BM * (K1 / 4); idx += NTHR) {
            int rr = idx / (K1 / 4);
            int q  = idx - rr * (K1 / 4);
            outr[(size_t)(row0 + rr) * (K1 / 4) + q] = tab[win[rr] * (K1 / 4) + q];
        }
    }
}

extern "C" void kernel_launch(void* const* d_in, const int* in_sizes, int n_in,
                              void* d_out, int out_size) {
    const float* x    = (const float*)d_in[0];
    const float* We1  = (const float*)d_in[1];
    const float* be1  = (const float*)d_in[2];
    const float* We2  = (const float*)d_in[3];
    const float* be2  = (const float*)d_in[4];
    const float* Wd1  = (const float*)d_in[5];
    const float* bd1  = (const float*)d_in[6];
    const float* Wd2  = (const float*)d_in[7];
    const float* bd2  = (const float*)d_in[8];
    const float* prot = (const float*)d_in[9];
    float* out = (float*)d_out;

    decoder_table_kernel<<<NPROTO, NTHR>>>(Wd1, bd1, Wd2, bd2, prot);

    cudaFuncSetAttribute(dpsom_main_kernel,
                         cudaFuncAttributeMaxDynamicSharedMemorySize, SMEM_BYTES);
    dpsom_main_kernel<<<BATCH / BM, NTHR, SMEM_BYTES>>>(x, We1, be1, We2, be2, prot, out);
}

// round 4
// speedup vs baseline: 1.2274x; 1.2274x over previous
#include <cuda_runtime.h>

// ---------------------------------------------------------------------------
// DPSOM fused kernel, round 4: register-tiled fp32 GEMM1 (8x8 per thread,
// FFMA2:LDS = 8:1) replacing R3's LDS-bound loop (which profiled L1=89%,
// fma=33%). Accumulation order per output is IDENTICAL to R3 (sequential
// k=0..783, one packed-FMA lane per k) -> h and z are bit-identical to the
// passing R3 kernel -> argmin behavior preserved exactly.
//   CTA: 128 rows x 256 hidden cols, 512 threads, BK=8 double-buffered smem.
//   Epilogue (GEMM2, SOM argmin, decoder-table gather) as in R3, BM=128.
//   output layout: [x_recon (B*784) | z (B*32) | som_z (B*32)]  (fp32)
// ---------------------------------------------------------------------------

#define BATCH   65536
#define K1      784
#define HID     256
#define LAT     32
#define NPROTO  25
#define BM      128
#define BK      8
#define NTHR    512
#define NCHUNK  (K1 / BK)           // 98

#define HSTRIDE 257                 // pad: GEMM2 h reads conflict-free
#define OFF_B   (BM * HSTRIDE)      // 32896 floats: h region first

// stage buffers inside region B (aliased by epilogue arrays afterwards)
#define XS_STRIDE 132               // pad: transpose-store conflict-free
#define XS_STAGE  (BK * XS_STRIDE)  // 1056
#define WS_OFF    (2 * XS_STAGE)    // 2112
#define WS_STAGE  (BK * HID)        // 2048

// epilogue arrays inside region B
#define EP_WE2   0                              // 8192 floats
#define EP_ZS    8192                           // 4096
#define EP_DS    (EP_ZS + BM * LAT)             // 12288 (3200)
#define EP_PROTO (EP_DS + BM * NPROTO)          // 15488 (800)
#define EP_PN    (EP_PROTO + NPROTO * LAT)      // 16288 (32 padded)
#define EP_ZZ    (EP_PN + 32)                   // 16320 (128)
#define EP_WIN   (EP_ZZ + BM)                   // 16448 (128)
#define B_FLOATS (EP_WIN + BM)                  // 16576

#define SMEM_FLOATS (OFF_B + B_FLOATS)          // 49472
#define SMEM_BYTES  (SMEM_FLOATS * 4)           // 197888

typedef unsigned long long ull;

// Decoder table: sigmoid(relu(proto @ Wd1 + bd1) @ Wd2 + bd2), per prototype.
__device__ float4 g_recon_table4[NPROTO * (K1 / 4)];

__global__ void decoder_table_kernel(const float* __restrict__ Wd1,
                                     const float* __restrict__ bd1,
                                     const float* __restrict__ Wd2,
                                     const float* __restrict__ bd2,
                                     const float* __restrict__ proto) {
    __shared__ float p[LAT];
    __shared__ float hd[HID];
    const int pid = blockIdx.x;
    const int t = threadIdx.x;
    if (t < LAT) p[t] = proto[pid * LAT + t];
    __syncthreads();
    if (t < HID) {
        float acc = 0.0f;
#pragma unroll
        for (int l = 0; l < LAT; l++) acc = fmaf(p[l], Wd1[l * HID + t], acc);
        hd[t] = fmaxf(acc + bd1[t], 0.0f);
    }
    __syncthreads();
    float* gt = (float*)g_recon_table4;
    for (int o = t; o < K1; o += 256) {
        float acc = 0.0f;
#pragma unroll 8
        for (int n = 0; n < HID; n++) acc = fmaf(hd[n], Wd2[n * K1 + o], acc);
        float v = acc + bd2[o];
        gt[pid * K1 + o] = 1.0f / (1.0f + expf(-v));
    }
}

__global__ void __launch_bounds__(NTHR, 1)
dpsom_main_kernel(const float* __restrict__ x,
                  const float* __restrict__ We1,
                  const float* __restrict__ be1,
                  const float* __restrict__ We2,
                  const float* __restrict__ be2,
                  const float* __restrict__ proto,
                  float* __restrict__ out) {
    extern __shared__ float sm[];
    float* hS = sm;              // [BM][HSTRIDE]
    float* bB = sm + OFF_B;      // region B

    const int t    = threadIdx.x;
    const int lane = t & 31;
    const int w    = t >> 5;
    // warp grid 4x4 (wm, wn); lane grid 4x8 (tm_l, tn_l)
    const int row_t = ((w & 3) * 4 + (lane & 3)) * 8;       // 0..120
    const int col_t = ((w >> 2) * 8 + (lane >> 2)) * 8;     // 0..248
    const size_t row0 = (size_t)blockIdx.x * BM;

    // loader roles
    const int xrow = t >> 1, xq = t & 1;    // t<256: x tile loader
    const int wk   = t >> 6, wq = t & 63;   // all:   w tile loader

    // ---- prologue: load + store chunk 0 into stage 0 ----
    float4 rx, rw;
    if (t < 256) rx = *(const float4*)(x + (row0 + xrow) * K1 + xq * 4);
    rw = *(const float4*)(We1 + wk * HID + wq * 4);
    {
        float* xb = bB;
        float* wb = bB + WS_OFF;
        if (t < 256) {
            xb[(xq * 4 + 0) * XS_STRIDE + xrow] = rx.x;
            xb[(xq * 4 + 1) * XS_STRIDE + xrow] = rx.y;
            xb[(xq * 4 + 2) * XS_STRIDE + xrow] = rx.z;
            xb[(xq * 4 + 3) * XS_STRIDE + xrow] = rx.w;
        }
        *(float4*)(wb + wk * HID + wq * 4) = rw;
    }
    __syncthreads();

    // ---- mainloop ----
    ull acc[32];
#pragma unroll
    for (int i = 0; i < 32; i++) acc[i] = 0ull;

    int st = 0;
#pragma unroll 1
    for (int kk = 0; kk < NCHUNK; kk++) {
        const bool notlast = (kk + 1 < NCHUNK);
        if (notlast) {
            const int kn = (kk + 1) * BK;
            if (t < 256) rx = *(const float4*)(x + (row0 + xrow) * K1 + kn + xq * 4);
            rw = *(const float4*)(We1 + (kn + wk) * HID + wq * 4);
        }
        const float* xb = bB + st * XS_STAGE;
        const float* wb = bB + WS_OFF + st * WS_STAGE;
#pragma unroll
        for (int k = 0; k < BK; k++) {
            const float* xk = xb + k * XS_STRIDE + row_t;
            const float* wn_ = wb + k * HID + col_t;
            ulonglong2 xv0 = *(const ulonglong2*)xk;         // rows r..r+3
            ulonglong2 xv1 = *(const ulonglong2*)(xk + 4);   // rows r+4..r+7
            float4 wv0 = *(const float4*)wn_;
            float4 wv1 = *(const float4*)(wn_ + 4);
            ull wd[8];
            asm("mov.b64 %0,{%1,%1};" : "=l"(wd[0]) : "f"(wv0.x));
            asm("mov.b64 %0,{%1,%1};" : "=l"(wd[1]) : "f"(wv0.y));
            asm("mov.b64 %0,{%1,%1};" : "=l"(wd[2]) : "f"(wv0.z));
            asm("mov.b64 %0,{%1,%1};" : "=l"(wd[3]) : "f"(wv0.w));
            asm("mov.b64 %0,{%1,%1};" : "=l"(wd[4]) : "f"(wv1.x));
            asm("mov.b64 %0,{%1,%1};" : "=l"(wd[5]) : "f"(wv1.y));
            asm("mov.b64 %0,{%1,%1};" : "=l"(wd[6]) : "f"(wv1.z));
            asm("mov.b64 %0,{%1,%1};" : "=l"(wd[7]) : "f"(wv1.w));
            ull xp[4];
            xp[0] = xv0.x; xp[1] = xv0.y; xp[2] = xv1.x; xp[3] = xv1.y;
#pragma unroll
            for (int p = 0; p < 4; p++)
#pragma unroll
                for (int j = 0; j < 8; j++)
                    asm("fma.rn.f32x2 %0, %1, %2, %0;"
                        : "+l"(acc[p * 8 + j]) : "l"(xp[p]), "l"(wd[j]));
        }
        if (notlast) {
            float* xb2 = bB + (st ^ 1) * XS_STAGE;
            float* wb2 = bB + WS_OFF + (st ^ 1) * WS_STAGE;
            if (t < 256) {
                xb2[(xq * 4 + 0) * XS_STRIDE + xrow] = rx.x;
                xb2[(xq * 4 + 1) * XS_STRIDE + xrow] = rx.y;
                xb2[(xq * 4 + 2) * XS_STRIDE + xrow] = rx.z;
                xb2[(xq * 4 + 3) * XS_STRIDE + xrow] = rx.w;
            }
            *(float4*)(wb2 + wk * HID + wq * 4) = rw;
            __syncthreads();
            st ^= 1;
        }
    }

    // ---- h = relu(acc + bias) -> smem (region A) ----
    {
        float bias[8];
        *(float4*)bias       = *(const float4*)(be1 + col_t);
        *(float4*)(bias + 4) = *(const float4*)(be1 + col_t + 4);
#pragma unroll
        for (int p = 0; p < 4; p++)
#pragma unroll
            for (int j = 0; j < 8; j++) {
                float lo, hi;
                asm("mov.b64 {%0,%1},%2;" : "=f"(lo), "=f"(hi) : "l"(acc[p * 8 + j]));
                hS[(row_t + 2 * p) * HSTRIDE + col_t + j]     = fmaxf(lo + bias[j], 0.0f);
                hS[(row_t + 2 * p + 1) * HSTRIDE + col_t + j] = fmaxf(hi + bias[j], 0.0f);
            }
    }
    __syncthreads();   // stage buffers dead; region B becomes epilogue arrays

    float* we2s = bB + EP_WE2;
    float* zsS  = bB + EP_ZS;
    float* dsS  = bB + EP_DS;
    float* prS  = bB + EP_PROTO;
    float* pnS  = bB + EP_PN;
    float* zzS  = bB + EP_ZZ;
    int*   winS = (int*)(bB + EP_WIN);

    for (int i = t; i < HID * LAT; i += NTHR) we2s[i] = We2[i];
    for (int i = t; i < NPROTO * LAT; i += NTHR) prS[i] = proto[i];
    __syncthreads();

    // ---- GEMM2: thread -> (row r, 8 latent cols); bias in epilogue ----
    {
        const int r    = t >> 2;
        const int latb = (t & 3) * 8;
        ull a0 = 0, a1 = 0, a2 = 0, a3 = 0;
        const float* hr    = hS + r * HSTRIDE;
        const float* wbase = we2s + latb;
#pragma unroll 8
        for (int n = 0; n < HID; n++) {
            float hv = hr[n];
            ull hd;
            asm("mov.b64 %0,{%1,%1};" : "=l"(hd) : "f"(hv));
            ulonglong2 w0 = *(const ulonglong2*)(wbase + n * LAT);
            ulonglong2 w1 = *(const ulonglong2*)(wbase + n * LAT + 4);
            asm("fma.rn.f32x2 %0, %1, %2, %0;" : "+l"(a0) : "l"(hd), "l"(w0.x));
            asm("fma.rn.f32x2 %0, %1, %2, %0;" : "+l"(a1) : "l"(hd), "l"(w0.y));
            asm("fma.rn.f32x2 %0, %1, %2, %0;" : "+l"(a2) : "l"(hd), "l"(w1.x));
            asm("fma.rn.f32x2 %0, %1, %2, %0;" : "+l"(a3) : "l"(hd), "l"(w1.y));
        }
        float z[8];
        asm("mov.b64 {%0,%1},%2;" : "=f"(z[0]), "=f"(z[1]) : "l"(a0));
        asm("mov.b64 {%0,%1},%2;" : "=f"(z[2]), "=f"(z[3]) : "l"(a1));
        asm("mov.b64 {%0,%1},%2;" : "=f"(z[4]), "=f"(z[5]) : "l"(a2));
        asm("mov.b64 {%0,%1},%2;" : "=f"(z[6]), "=f"(z[7]) : "l"(a3));
        float bz[8];
        *(float4*)bz       = *(const float4*)(be2 + latb);
        *(float4*)(bz + 4) = *(const float4*)(be2 + latb + 4);
#pragma unroll
        for (int j = 0; j < 8; j++) z[j] += bz[j];
        *(float4*)(zsS + r * LAT + latb)     = *(float4*)z;
        *(float4*)(zsS + r * LAT + latb + 4) = *(float4*)(z + 4);
        float* out_z = out + (size_t)BATCH * K1;
        *(float4*)(out_z + (row0 + r) * LAT + latb)     = *(float4*)z;
        *(float4*)(out_z + (row0 + r) * LAT + latb + 4) = *(float4*)(z + 4);
    }
    __syncthreads();

    // ---- pp_j (warp-shuffle-tree order, as R3) and zz per row ----
    if (t < NPROTO) {
        const float* pj = prS + t * LAT;
        float a[32];
#pragma unroll
        for (int l = 0; l < 32; l++) a[l] = pj[l] * pj[l];
#pragma unroll
        for (int off = 16; off >= 1; off >>= 1)
#pragma unroll
            for (int i = 0; i < 16; i++)
                if (i < off) a[i] += a[i + off];
        pnS[t] = a[0];
    }
    if (t >= 128 && t < 128 + BM) {
        int rr = t - 128;
        const float* zr = zsS + rr * LAT;
        float s = 0.0f;
#pragma unroll
        for (int l = 0; l < LAT; l++) s = fmaf(zr[l], zr[l], s);
        zzS[rr] = s;
    }
    __syncthreads();

    // ---- distances (reference form): d = (zz - 2*dot) + pp ----
    for (int idx = t; idx < BM * NPROTO; idx += NTHR) {
        int rr = idx / NPROTO;
        int j  = idx - rr * NPROTO;
        const float* zr = zsS + rr * LAT;
        const float* pj = prS + j * LAT;
        float dot = 0.0f;
#pragma unroll
        for (int l = 0; l < LAT; l++) dot = fmaf(zr[l], pj[l], dot);
        dsS[idx] = (zzS[rr] - 2.0f * dot) + pnS[j];
    }
    __syncthreads();

    // ---- argmin per row (strict <, first-min like jnp.argmin) ----
    if (t < BM) {
        const float* dr = dsS + t * NPROTO;
        float best = dr[0];
        int bi = 0;
#pragma unroll
        for (int j = 1; j < NPROTO; j++) {
            float v = dr[j];
            if (v < best) { best = v; bi = j; }
        }
        winS[t] = bi;
    }
    __syncthreads();

    // ---- som_z + x_recon (gather from decoder table) ----
    {
        float* out_som = out + (size_t)BATCH * (K1 + LAT);
        for (int idx = t; idx < BM * LAT; idx += NTHR) {
            int rr = idx >> 5, l = idx & (LAT - 1);
            out_som[(row0 + rr) * LAT + l] = prS[winS[rr] * LAT + l];
        }
        const float4* tab = (const float4*)g_recon_table4;
        float4* outr = (float4*)out;
        for (int idx = t; idx < BM * (K1 / 4); idx += NTHR) {
            int rr = idx / (K1 / 4);
            int q  = idx - rr * (K1 / 4);
            outr[(row0 + rr) * (K1 / 4) + q] = tab[winS[rr] * (K1 / 4) + q];
        }
    }
}

extern "C" void kernel_launch(void* const* d_in, const int* in_sizes, int n_in,
                              void* d_out, int out_size) {
    const float* x    = (const float*)d_in[0];
    const float* We1  = (const float*)d_in[1];
    const float* be1  = (const float*)d_in[2];
    const float* We2  = (const float*)d_in[3];
    const float* be2  = (const float*)d_in[4];
    const float* Wd1  = (const float*)d_in[5];
    const float* bd1  = (const float*)d_in[6];
    const float* Wd2  = (const float*)d_in[7];
    const float* bd2  = (const float*)d_in[8];
    const float* prot = (const float*)d_in[9];
    float* out = (float*)d_out;

    decoder_table_kernel<<<NPROTO, 256>>>(Wd1, bd1, Wd2, bd2, prot);

    cudaFuncSetAttribute(dpsom_main_kernel,
                         cudaFuncAttributeMaxDynamicSharedMemorySize, SMEM_BYTES);
    dpsom_main_kernel<<<BATCH / BM, NTHR, SMEM_BYTES>>>(x, We1, be1, We2, be2, prot, out);
}

// round 6
// speedup vs baseline: 1.8521x; 1.5090x over previous
#include <cuda_runtime.h>
#include <cuda_bf16.h>

// ---------------------------------------------------------------------------
// DPSOM fused kernel, round 6.
// tcgen05 is unavailable (harness compiles via compute_103, no 'a'): GEMM1
// now uses mma.sync.m16n8k16 bf16 (HMMA, sm_80 baseline) with a 3-term
// bf16 split (x_hi*W_hi + x_hi*W_lo + x_lo*W_hi, fp32 accum), cp.async for
// pre-split/pre-swizzled W tiles, ldmatrix fragment loads.
// Gap-guarded argmin + exact-fp32 repair kernel (R5 design) retained.
//   output layout: [x_recon (B*784) | z (B*32) | som_z (B*32)]  (fp32)
// ---------------------------------------------------------------------------

#define BATCH   65536
#define K1      784
#define HID     256
#define LAT     32
#define NPROTO  25
#define BM      128
#define NTHR    512
#define NCH     13            // 13 x 64 = 832 >= 784, tail zero-padded
#define GUARD   4e-3f

// smem (bytes): [0..1024) be1 staging; [1024 + st*98304) stages:
//   A_hi 16KB | A_lo 16KB | B_hi 32KB | B_lo 32KB
// epilogue aliases stages after mainloop.
#define STG_BYTES  98304
#define HS_OFF     256                           // floats
#define HSTRIDE    257
#define EP_WE2     (HS_OFF + BM * HSTRIDE)       // 33152
#define EP_ZS      (EP_WE2 + HID * LAT)          // 41344
#define EP_DS      (EP_ZS + BM * LAT)            // 45440
#define EP_PROTO   (EP_DS + BM * NPROTO)         // 48640
#define EP_PN      (EP_PROTO + NPROTO * LAT)     // 49440
#define EP_ZZ      (EP_PN + 32)                  // 49472
#define EP_WIN     (EP_ZZ + BM)                  // 49600
#define SMEM_FLOATS (EP_WIN + BM)                // 49728
#define SMEM_BYTES  (SMEM_FLOATS * 4)            // 198912

typedef unsigned long long u64;
typedef unsigned int u32;

// W pre-converted + pre-swizzled [n][k] tiles: [chunk][32KB image]
__device__ uint4 g_Bhi[NCH * 2048];
__device__ uint4 g_Blo[NCH * 2048];
__device__ float4 g_recon_table4[NPROTO * (K1 / 4)];
__device__ int    g_repair_count;
__device__ int    g_repair_rows[BATCH];

__host__ __device__ __forceinline__ u32 swz(u32 b) { return b ^ ((b >> 3) & 0x70); }

__device__ __forceinline__ u32 su(const void* p) {
    u32 a;
    asm("{ .reg .u64 t; cvta.to.shared.u64 t, %1; cvt.u32.u64 %0, t; }" : "=r"(a) : "l"(p));
    return a;
}
__device__ __forceinline__ void ldsm4(u32 a, u32& r0, u32& r1, u32& r2, u32& r3) {
    asm volatile("ldmatrix.sync.aligned.m8n8.x4.shared.b16 {%0,%1,%2,%3}, [%4];"
                 : "=r"(r0), "=r"(r1), "=r"(r2), "=r"(r3) : "r"(a));
}
__device__ __forceinline__ void mma16816(float* c, const u32* a, u32 b0, u32 b1) {
    asm volatile("mma.sync.aligned.m16n8k16.row.col.f32.bf16.bf16.f32 "
                 "{%0,%1,%2,%3},{%4,%5,%6,%7},{%8,%9},{%0,%1,%2,%3};"
                 : "+f"(c[0]), "+f"(c[1]), "+f"(c[2]), "+f"(c[3])
                 : "r"(a[0]), "r"(a[1]), "r"(a[2]), "r"(a[3]), "r"(b0), "r"(b1));
}
__device__ __forceinline__ void cpasync16(u32 dst, const void* src) {
    asm volatile("cp.async.cg.shared.global [%0], [%1], 16;" :: "r"(dst), "l"(src));
}
#define CP_COMMIT() asm volatile("cp.async.commit_group;")
#define CP_WAIT0()  asm volatile("cp.async.wait_group 0;")

// ---------------- prep kernels ----------------
__global__ void zero_flags_kernel() { g_repair_count = 0; }

__global__ void prep_w_kernel(const float* __restrict__ We1) {
    const int c = blockIdx.x;
    __nv_bfloat16* bh = (__nv_bfloat16*)g_Bhi;
    __nv_bfloat16* bl = (__nv_bfloat16*)g_Blo;
    for (int idx = threadIdx.x; idx < 256 * 64; idx += blockDim.x) {
        int n = idx >> 6, kp = idx & 63;
        int k = c * 64 + kp;
        float v = (k < K1) ? We1[k * HID + n] : 0.0f;
        __nv_bfloat16 hi = __float2bfloat16(v);
        __nv_bfloat16 lo = __float2bfloat16(v - __bfloat162float(hi));
        u32 off = (u32)c * 32768u + swz((u32)n * 128u + (u32)kp * 2u);
        bh[off >> 1] = hi;
        bl[off >> 1] = lo;
    }
}

__global__ void decoder_table_kernel(const float* __restrict__ Wd1,
                                     const float* __restrict__ bd1,
                                     const float* __restrict__ Wd2,
                                     const float* __restrict__ bd2,
                                     const float* __restrict__ proto) {
    __shared__ float p[LAT];
    __shared__ float hd[HID];
    const int pid = blockIdx.x;
    const int t = threadIdx.x;
    if (t < LAT) p[t] = proto[pid * LAT + t];
    __syncthreads();
    if (t < HID) {
        float acc = 0.0f;
#pragma unroll
        for (int l = 0; l < LAT; l++) acc = fmaf(p[l], Wd1[l * HID + t], acc);
        hd[t] = fmaxf(acc + bd1[t], 0.0f);
    }
    __syncthreads();
    float* gt = (float*)g_recon_table4;
    for (int o = t; o < K1; o += 256) {
        float acc = 0.0f;
#pragma unroll 8
        for (int n = 0; n < HID; n++) acc = fmaf(hd[n], Wd2[n * K1 + o], acc);
        float v = acc + bd2[o];
        gt[pid * K1 + o] = 1.0f / (1.0f + expf(-v));
    }
}

// ---------------- main kernel ----------------
__global__ void __launch_bounds__(NTHR)
dpsom_main_kernel(const float* __restrict__ x,
                  const float* __restrict__ be1,
                  const float* __restrict__ We2,
                  const float* __restrict__ be2,
                  const float* __restrict__ proto,
                  float* __restrict__ out) {
    extern __shared__ float sm[];
    const u32 sb = su(sm);
    const int t = threadIdx.x, lane = t & 31, w = t >> 5;
    const int wr = w >> 2, wc = w & 3;          // warp grid 4x4
    const size_t row0 = (size_t)blockIdx.x * BM;

    // A loader role: row ar (0..127), k-quarter aq (16 k each)
    const int ar = t >> 2, aq = t & 3;
    // B fragment lane decode
    const u32 bn  = (u32)((lane & 7) + ((lane & 16) ? 8 : 0));
    const u32 bkb = (u32)(((lane >> 3) & 1) * 16);

    if (t < HID) sm[t] = be1[t];   // be1 staging (floats 0..255)

    float4 va[4];
    // ---- A chunk loader/converter (stores into given stage) ----
    auto loadA = [&](int c) {
        const float4* xp = (const float4*)(x + (row0 + ar) * K1 + c * 64 + aq * 16);
#pragma unroll
        for (int j = 0; j < 4; j++) {
            int kk = c * 64 + aq * 16 + j * 4;
            float4 v = make_float4(0.f, 0.f, 0.f, 0.f);
            if (kk < K1) v = xp[j];
            va[j] = v;
        }
    };
    auto storeA = [&](int st) {
        char* Sb = (char*)sm + 1024 + st * STG_BYTES;
#pragma unroll
        for (int j = 0; j < 4; j++) {
            float4 v = va[j];
            __nv_bfloat16 hx = __float2bfloat16(v.x), hy = __float2bfloat16(v.y);
            __nv_bfloat16 hz = __float2bfloat16(v.z), hw = __float2bfloat16(v.w);
            __nv_bfloat16 lx = __float2bfloat16(v.x - __bfloat162float(hx));
            __nv_bfloat16 ly = __float2bfloat16(v.y - __bfloat162float(hy));
            __nv_bfloat16 lz = __float2bfloat16(v.z - __bfloat162float(hz));
            __nv_bfloat16 lw = __float2bfloat16(v.w - __bfloat162float(hw));
            uint2 hv, lv;
            hv.x = (u32)__bfloat16_as_ushort(hx) | ((u32)__bfloat16_as_ushort(hy) << 16);
            hv.y = (u32)__bfloat16_as_ushort(hz) | ((u32)__bfloat16_as_ushort(hw) << 16);
            lv.x = (u32)__bfloat16_as_ushort(lx) | ((u32)__bfloat16_as_ushort(ly) << 16);
            lv.y = (u32)__bfloat16_as_ushort(lz) | ((u32)__bfloat16_as_ushort(lw) << 16);
            u32 o = swz((u32)ar * 128u + (u32)((aq * 16 + j * 4) * 2));
            *(uint2*)(Sb + o)         = hv;
            *(uint2*)(Sb + 16384 + o) = lv;
        }
    };
    auto loadB = [&](int c, int st) {
        const uint4* gh = g_Bhi + c * 2048;
        const uint4* gl = g_Blo + c * 2048;
        u32 dh = sb + 1024 + st * STG_BYTES + 32768;
        u32 dl = dh + 32768;
#pragma unroll
        for (int j = 0; j < 4; j++) {
            int o = j * NTHR + t;
            cpasync16(dh + o * 16, gh + o);
            cpasync16(dl + o * 16, gl + o);
        }
        CP_COMMIT();
    };

    // ---- prologue ----
    loadA(0); storeA(0); loadB(0, 0);
    CP_WAIT0();
    __syncthreads();

    float acc[2][8][4];
#pragma unroll
    for (int m = 0; m < 2; m++)
#pragma unroll
        for (int n = 0; n < 8; n++)
#pragma unroll
            for (int q = 0; q < 4; q++) acc[m][n][q] = 0.0f;

#pragma unroll 1
    for (int c = 0; c < NCH; c++) {
        const int st = c & 1;
        if (c + 1 < NCH) { loadB(c + 1, st ^ 1); loadA(c + 1); }

        const u32 SB  = sb + 1024 + st * STG_BYTES;
        const u32 Ahi = SB, Alo = SB + 16384, Bhi = SB + 32768, Blo = SB + 65536;
        const u32 arow = (u32)((wr * 32 + (lane & 15)) * 128) + ((u32)(lane >> 4) << 4);
#pragma unroll
        for (int ks = 0; ks < 4; ks++) {
            const u32 kb = (u32)ks * 32u;
            u32 ah[8], al[8];
            {
                u32 o0 = arow + kb, o1 = o0 + 2048;
                ldsm4(Ahi + swz(o0), ah[0], ah[1], ah[2], ah[3]);
                ldsm4(Ahi + swz(o1), ah[4], ah[5], ah[6], ah[7]);
                ldsm4(Alo + swz(o0), al[0], al[1], al[2], al[3]);
                ldsm4(Alo + swz(o1), al[4], al[5], al[6], al[7]);
            }
#pragma unroll
            for (int half = 0; half < 2; half++) {
                u32 bh[8], bl[8];
#pragma unroll
                for (int pr = 0; pr < 2; pr++) {
                    u32 o = (u32)((wc * 64 + half * 32 + pr * 16 + bn) * 128) + kb + bkb;
                    ldsm4(Bhi + swz(o), bh[pr*4+0], bh[pr*4+1], bh[pr*4+2], bh[pr*4+3]);
                    ldsm4(Blo + swz(o), bl[pr*4+0], bl[pr*4+1], bl[pr*4+2], bl[pr*4+3]);
                }
#pragma unroll
                for (int m = 0; m < 2; m++)
#pragma unroll
                    for (int nt = 0; nt < 4; nt++) {
                        float* cc = acc[m][half * 4 + nt];
                        u32 b0 = bh[(nt >> 1) * 4 + (nt & 1) * 2];
                        u32 b1 = bh[(nt >> 1) * 4 + (nt & 1) * 2 + 1];
                        u32 c0 = bl[(nt >> 1) * 4 + (nt & 1) * 2];
                        u32 c1 = bl[(nt >> 1) * 4 + (nt & 1) * 2 + 1];
                        mma16816(cc, &ah[m * 4], b0, b1);
                        mma16816(cc, &ah[m * 4], c0, c1);
                        mma16816(cc, &al[m * 4], b0, b1);
                    }
            }
        }
        if (c + 1 < NCH) storeA(st ^ 1);
        CP_WAIT0();
        __syncthreads();
    }

    // ---- h = relu(acc + be1) -> hS ----
    float* hS = sm + HS_OFF;
    {
        const int g = lane >> 2, tq = (lane & 3) * 2;
#pragma unroll
        for (int m = 0; m < 2; m++)
#pragma unroll
            for (int nt = 0; nt < 8; nt++) {
                int row = wr * 32 + m * 16 + g;
                int col = wc * 64 + nt * 8 + tq;
                float b0 = sm[col], b1 = sm[col + 1];
                float* cc = acc[m][nt];
                hS[row * HSTRIDE + col]           = fmaxf(cc[0] + b0, 0.0f);
                hS[row * HSTRIDE + col + 1]       = fmaxf(cc[1] + b1, 0.0f);
                hS[(row + 8) * HSTRIDE + col]     = fmaxf(cc[2] + b0, 0.0f);
                hS[(row + 8) * HSTRIDE + col + 1] = fmaxf(cc[3] + b1, 0.0f);
            }
    }
    float* we2s = sm + EP_WE2;
    float* zsS  = sm + EP_ZS;
    float* dsS  = sm + EP_DS;
    float* prS  = sm + EP_PROTO;
    float* pnS  = sm + EP_PN;
    float* zzS  = sm + EP_ZZ;
    int*   winS = (int*)(sm + EP_WIN);
    for (int i = t; i < HID * LAT; i += NTHR) we2s[i] = We2[i];
    for (int i = t; i < NPROTO * LAT; i += NTHR) prS[i] = proto[i];
    __syncthreads();

    // ---- GEMM2 (fp32, R4 order): thread -> (row r, 8 lat cols) ----
    {
        float* out_z = out + (size_t)BATCH * K1;
        const int r = t >> 2;
        const int latb = (t & 3) * 8;
        u64 a0 = 0, a1 = 0, a2 = 0, a3 = 0;
        const float* hr = hS + r * HSTRIDE;
        const float* wbase = we2s + latb;
#pragma unroll 8
        for (int n = 0; n < HID; n++) {
            float hv = hr[n];
            u64 hd;
            asm("mov.b64 %0,{%1,%1};" : "=l"(hd) : "f"(hv));
            ulonglong2 w0 = *(const ulonglong2*)(wbase + n * LAT);
            ulonglong2 w1 = *(const ulonglong2*)(wbase + n * LAT + 4);
            asm("fma.rn.f32x2 %0, %1, %2, %0;" : "+l"(a0) : "l"(hd), "l"(w0.x));
            asm("fma.rn.f32x2 %0, %1, %2, %0;" : "+l"(a1) : "l"(hd), "l"(w0.y));
            asm("fma.rn.f32x2 %0, %1, %2, %0;" : "+l"(a2) : "l"(hd), "l"(w1.x));
            asm("fma.rn.f32x2 %0, %1, %2, %0;" : "+l"(a3) : "l"(hd), "l"(w1.y));
        }
        float z[8];
        asm("mov.b64 {%0,%1},%2;" : "=f"(z[0]), "=f"(z[1]) : "l"(a0));
        asm("mov.b64 {%0,%1},%2;" : "=f"(z[2]), "=f"(z[3]) : "l"(a1));
        asm("mov.b64 {%0,%1},%2;" : "=f"(z[4]), "=f"(z[5]) : "l"(a2));
        asm("mov.b64 {%0,%1},%2;" : "=f"(z[6]), "=f"(z[7]) : "l"(a3));
        float bz[8];
        *(float4*)bz       = *(const float4*)(be2 + latb);
        *(float4*)(bz + 4) = *(const float4*)(be2 + latb + 4);
#pragma unroll
        for (int j = 0; j < 8; j++) z[j] += bz[j];
        *(float4*)(zsS + r * LAT + latb)     = *(float4*)z;
        *(float4*)(zsS + r * LAT + latb + 4) = *(float4*)(z + 4);
        *(float4*)(out_z + (row0 + r) * LAT + latb)     = *(float4*)z;
        *(float4*)(out_z + (row0 + r) * LAT + latb + 4) = *(float4*)(z + 4);
    }
    __syncthreads();

    // ---- pp (shuffle-tree order), zz, distances (reference form) ----
    if (t < NPROTO) {
        const float* pj = prS + t * LAT;
        float a[32];
#pragma unroll
        for (int l = 0; l < 32; l++) a[l] = pj[l] * pj[l];
#pragma unroll
        for (int off = 16; off >= 1; off >>= 1)
#pragma unroll
            for (int i = 0; i < 16; i++)
                if (i < off) a[i] += a[i + off];
        pnS[t] = a[0];
    }
    if (t >= 128 && t < 128 + BM) {
        int rr = t - 128;
        const float* zr = zsS + rr * LAT;
        float s = 0.0f;
#pragma unroll
        for (int l = 0; l < LAT; l++) s = fmaf(zr[l], zr[l], s);
        zzS[rr] = s;
    }
    __syncthreads();
    for (int idx = t; idx < BM * NPROTO; idx += NTHR) {
        int rr = idx / NPROTO;
        int j  = idx - rr * NPROTO;
        const float* zr = zsS + rr * LAT;
        const float* pj = prS + j * LAT;
        float dot = 0.0f;
#pragma unroll
        for (int l = 0; l < LAT; l++) dot = fmaf(zr[l], pj[l], dot);
        dsS[idx] = (zzS[rr] - 2.0f * dot) + pnS[j];
    }
    __syncthreads();

    // ---- argmin + gap guard -> repair list ----
    if (t < BM) {
        const float* dr = dsS + t * NPROTO;
        float best = dr[0], sec = 3.4e38f;
        int bi = 0;
#pragma unroll
        for (int j = 1; j < NPROTO; j++) {
            float v = dr[j];
            if (v < best) { sec = best; best = v; bi = j; }
            else if (v < sec) sec = v;
        }
        winS[t] = bi;
        if (sec - best < GUARD) {
            int idx = atomicAdd(&g_repair_count, 1);
            if (idx < BATCH) g_repair_rows[idx] = (int)(row0 + t);
        }
    }
    __syncthreads();

    // ---- som_z + x_recon (provisional; repair overwrites flagged rows) ----
    {
        float* out_som = out + (size_t)BATCH * (K1 + LAT);
        for (int idx = t; idx < BM * LAT; idx += NTHR) {
            int rr = idx >> 5, l = idx & (LAT - 1);
            out_som[(row0 + rr) * LAT + l] = prS[winS[rr] * LAT + l];
        }
        const float4* tab = (const float4*)g_recon_table4;
        float4* outr = (float4*)out;
        for (int idx = t; idx < BM * (K1 / 4); idx += NTHR) {
            int rr = idx / (K1 / 4);
            int q  = idx - rr * (K1 / 4);
            outr[(row0 + rr) * (K1 / 4) + q] = tab[winS[rr] * (K1 / 4) + q];
        }
    }
}

// ---------------- repair kernel: exact fp32 path (R3/R4 order) ----------------
#define RROWS 8
__global__ void __launch_bounds__(256)
repair_kernel(const float* __restrict__ x,
              const float* __restrict__ We1,
              const float* __restrict__ be1,
              const float* __restrict__ We2,
              const float* __restrict__ be2,
              const float* __restrict__ proto,
              float* __restrict__ out) {
    __shared__ float xr[RROWS][K1];
    __shared__ float h8[RROWS][HSTRIDE];
    __shared__ float z8[RROWS][LAT];
    __shared__ float pp[32];
    __shared__ float dd[RROWS * 32];
    __shared__ int   rows[RROWS];
    __shared__ int   win8[RROWS];
    const int t = threadIdx.x;
    int cnt = g_repair_count;
    if (cnt > BATCH) cnt = BATCH;

    for (int g = blockIdx.x; g * RROWS < cnt; g += gridDim.x) {
        const int nr = min(RROWS, cnt - g * RROWS);
        if (t < nr) rows[t] = g_repair_rows[g * RROWS + t];
        __syncthreads();
        for (int i = t; i < nr * K1; i += 256) {
            int rr = i / K1, k = i - rr * K1;
            xr[rr][k] = x[(size_t)rows[rr] * K1 + k];
        }
        __syncthreads();
        {
            float acc[RROWS];
#pragma unroll
            for (int rr = 0; rr < RROWS; rr++) acc[rr] = 0.0f;
#pragma unroll 4
            for (int k = 0; k < K1; k++) {
                float wv = We1[k * HID + t];
#pragma unroll
                for (int rr = 0; rr < RROWS; rr++)
                    acc[rr] = fmaf(xr[rr][k], wv, acc[rr]);
            }
            float b = be1[t];
#pragma unroll
            for (int rr = 0; rr < RROWS; rr++)
                h8[rr][t] = fmaxf(acc[rr] + b, 0.0f);
        }
        __syncthreads();
        if (t < nr * LAT) {
            int rr = t >> 5, l = t & 31;
            float a = 0.0f;
#pragma unroll 8
            for (int n = 0; n < HID; n++) a = fmaf(h8[rr][n], We2[n * LAT + l], a);
            a += be2[l];
            z8[rr][l] = a;
            out[(size_t)BATCH * K1 + (size_t)rows[rr] * LAT + l] = a;
        }
        if (t >= 224 && t < 224 + NPROTO) {
            int j = t - 224;
            const float* pj = proto + j * LAT;
            float a[32];
#pragma unroll
            for (int l = 0; l < 32; l++) a[l] = pj[l] * pj[l];
#pragma unroll
            for (int off = 16; off >= 1; off >>= 1)
#pragma unroll
                for (int i = 0; i < 16; i++)
                    if (i < off) a[i] += a[i + off];
            pp[j] = a[0];
        }
        __syncthreads();
        if (t < nr * NPROTO) {
            int rr = t / NPROTO, j = t - rr * NPROTO;
            const float* zr = z8[rr];
            const float* pj = proto + j * LAT;
            float zz = 0.0f, dot = 0.0f;
#pragma unroll
            for (int l = 0; l < LAT; l++) zz = fmaf(zr[l], zr[l], zz);
#pragma unroll
            for (int l = 0; l < LAT; l++) dot = fmaf(zr[l], pj[l], dot);
            dd[rr * 32 + j] = (zz - 2.0f * dot) + pp[j];
        }
        __syncthreads();
        if (t < nr) {
            const float* dr = dd + t * 32;
            float best = dr[0];
            int bi = 0;
#pragma unroll
            for (int j = 1; j < NPROTO; j++) {
                float v = dr[j];
                if (v < best) { best = v; bi = j; }
            }
            win8[t] = bi;
        }
        __syncthreads();
        for (int i = t; i < nr * LAT; i += 256) {
            int rr = i >> 5, l = i & 31;
            out[(size_t)BATCH * (K1 + LAT) + (size_t)rows[rr] * LAT + l] =
                proto[win8[rr] * LAT + l];
        }
        const float4* tab = (const float4*)g_recon_table4;
        float4* outr = (float4*)out;
        for (int i = t; i < nr * (K1 / 4); i += 256) {
            int rr = i / (K1 / 4), q = i - rr * (K1 / 4);
            outr[(size_t)rows[rr] * (K1 / 4) + q] = tab[win8[rr] * (K1 / 4) + q];
        }
        __syncthreads();
    }
}

extern "C" void kernel_launch(void* const* d_in, const int* in_sizes, int n_in,
                              void* d_out, int out_size) {
    const float* x    = (const float*)d_in[0];
    const float* We1  = (const float*)d_in[1];
    const float* be1  = (const float*)d_in[2];
    const float* We2  = (const float*)d_in[3];
    const float* be2  = (const float*)d_in[4];
    const float* Wd1  = (const float*)d_in[5];
    const float* bd1  = (const float*)d_in[6];
    const float* Wd2  = (const float*)d_in[7];
    const float* bd2  = (const float*)d_in[8];
    const float* prot = (const float*)d_in[9];
    float* out = (float*)d_out;

    zero_flags_kernel<<<1, 1>>>();
    prep_w_kernel<<<NCH, 256>>>(We1);
    decoder_table_kernel<<<NPROTO, 256>>>(Wd1, bd1, Wd2, bd2, prot);

    cudaFuncSetAttribute(dpsom_main_kernel,
                         cudaFuncAttributeMaxDynamicSharedMemorySize, SMEM_BYTES);
    dpsom_main_kernel<<<BATCH / BM, NTHR, SMEM_BYTES>>>(x, be1, We2, be2, prot, out);

    repair_kernel<<<256, 256>>>(x, We1, be1, We2, be2, prot, out);
}